// round 12
// baseline (speedup 1.0000x reference)
#include <cuda_runtime.h>
#include <cstdint>

#define NB 16384
#define NT 1024
#define HH 64
#define TPB 64                // 2 autonomous warps; 4 elements per warp
#define EPB 8
#define GRID (NB / EPB)       // 2048 blocks -> 4096 warps

#define L2E2 2.8853900817779268f   // 2*log2(e), folded into W1/b1/W2/b2

typedef unsigned long long u64;

static __device__ __forceinline__ u64 fma2(u64 a, u64 b, u64 c) {
    u64 d;
    asm("fma.rn.f32x2 %0, %1, %2, %3;" : "=l"(d) : "l"(a), "l"(b), "l"(c));
    return d;
}
static __device__ __forceinline__ u64 add2(u64 a, u64 b) {
    u64 d;
    asm("add.rn.f32x2 %0, %1, %2;" : "=l"(d) : "l"(a), "l"(b));
    return d;
}
static __device__ __forceinline__ u64 pk(float a, float b) {
    u64 d;
    asm("mov.b64 %0, {%1, %2};" : "=l"(d) : "f"(a), "f"(b));
    return d;
}
static __device__ __forceinline__ u64 dup2(float a) {
    u64 d;
    asm("mov.b64 %0, {%1, %1};" : "=l"(d) : "f"(a));
    return d;
}
static __device__ __forceinline__ void upk(u64 v, float& a, float& b) {
    asm("mov.b64 {%0, %1}, %2;" : "=f"(a), "=f"(b) : "l"(v));
}
static __device__ __forceinline__ u64 shfl_xor64(u64 v, int m) {
    uint32_t lo = (uint32_t)v, hi = (uint32_t)(v >> 32);
    lo = __shfl_xor_sync(0xffffffffu, lo, m);
    hi = __shfl_xor_sync(0xffffffffu, hi, m);
    return ((u64)hi << 32) | lo;
}
// tanh with prescaled arg a = 2*log2(e)*x: tanh(x) = 1 - 2/(2^a + 1).
// Validated at rel_err ~3e-7 over 1023 steps (rounds 1-11).
static __device__ __forceinline__ float tanh_pre(float a) {
    float e, r;
    asm("ex2.approx.f32 %0, %1;" : "=f"(e) : "f"(a));
    asm("rcp.approx.f32 %0, %1;" : "=f"(r) : "f"(e + 1.0f));
    return fmaf(-2.0f, r, 1.0f);
}

// Packed (dup'd) RK coefficients: no per-stage dup2 on the ALU pipe.
__device__ __constant__ float2 cA2[5][5] = {
    {{1.f/5, 1.f/5}, {0,0}, {0,0}, {0,0}, {0,0}},
    {{3.f/40, 3.f/40}, {9.f/40, 9.f/40}, {0,0}, {0,0}, {0,0}},
    {{44.f/45, 44.f/45}, {-56.f/15, -56.f/15}, {32.f/9, 32.f/9}, {0,0}, {0,0}},
    {{(float)(19372.0/6561.0), (float)(19372.0/6561.0)},
     {(float)(-25360.0/2187.0), (float)(-25360.0/2187.0)},
     {(float)(64448.0/6561.0), (float)(64448.0/6561.0)},
     {(float)(-212.0/729.0), (float)(-212.0/729.0)}, {0,0}},
    {{(float)(9017.0/3168.0), (float)(9017.0/3168.0)},
     {(float)(-355.0/33.0), (float)(-355.0/33.0)},
     {(float)(46732.0/5247.0), (float)(46732.0/5247.0)},
     {(float)(49.0/176.0), (float)(49.0/176.0)},
     {(float)(-5103.0/18656.0), (float)(-5103.0/18656.0)}},
};
__device__ __constant__ float2 cB2[5] = {
    {(float)(35.0/384.0), (float)(35.0/384.0)},
    {(float)(500.0/1113.0), (float)(500.0/1113.0)},
    {(float)(125.0/192.0), (float)(125.0/192.0)},
    {(float)(-2187.0/6784.0), (float)(-2187.0/6784.0)},
    {(float)(11.0/84.0), (float)(11.0/84.0)},
};

__global__ void __launch_bounds__(TPB, 5)
ode_kernel(const float* __restrict__ y0, const float* __restrict__ ts,
           const float* __restrict__ W1, const float* __restrict__ b1,
           const float* __restrict__ W2, const float* __restrict__ b2,
           const float* __restrict__ W3, const float* __restrict__ b3,
           float* __restrict__ out) {
    __shared__ float dts[NT];
    __shared__ __align__(16) float hb[2][4][HH];   // [warp][elem][k]
    __shared__ __align__(16) float sW1x[HH], sW1y[HH], sB1[HH];  // * L2E2

    const int tid = threadIdx.x;
    for (int i = tid; i < NT - 1; i += TPB) dts[i] = ts[i + 1] - ts[i];
    for (int i = tid; i < HH; i += TPB) {
        sW1x[i] = W1[2 * i] * L2E2;
        sW1y[i] = W1[2 * i + 1] * L2E2;
        sB1[i] = b1[i] * L2E2;
    }

    const int lane = tid & 31;
    const int w = tid >> 5;
    const int me = lane >> 3;        // this lane's element (0..3)
    const int o = lane & 7;          // layer-1 unit octet
    const int u0 = 8 * o;            // layer-1 units u0..u0+7 for element me
    const int j0 = 2 * lane;         // lane's 2 j's (all 64 k in regs)

    // ---- W2 into registers: 2 j x 32 k-parity pairs (128 regs) ----
    u64 w2r[2][32];
#pragma unroll
    for (int jp = 0; jp < 2; jp++) {
        const float4* row = (const float4*)(W2 + (j0 + jp) * HH);
#pragma unroll
        for (int q = 0; q < 16; q++) {
            const float4 v = row[q];
            w2r[jp][2 * q]     = pk(v.x * L2E2, v.y * L2E2);
            w2r[jp][2 * q + 1] = pk(v.z * L2E2, v.w * L2E2);
        }
    }
    const float b2r0 = b2[j0] * L2E2;
    const float b2r1 = b2[j0 + 1] * L2E2;
    const u64 w3r0 = pk(W3[j0], W3[HH + j0]);
    const u64 w3r1 = pk(W3[j0 + 1], W3[HH + j0 + 1]);
    const u64 b3p = pk(b3[0], b3[1]);

    const int e0 = blockIdx.x * EPB + w * 4;
    const int em = e0 + me;
    u64 yv = ((const u64*)y0)[em];   // packed (yx, yy) for lane's element
    u64* o8 = (u64*)out;
    if (o == 0) o8[em] = yv;         // SaveAt includes the initial state
    __syncthreads();                 // smem tables ready

    float* hw = &hb[w][0][0];
    float* hme = &hb[w][me][0];
    const int b4 = me >> 1, b3b = me & 1;

    for (int t = 0; t < NT - 1; t++) {
        const float dtv = dts[t];
        const u64 dtp = dup2(dtv);
        u64 kreg[6];

#pragma unroll 1
        for (int st = 0; st < 6; st++) {
            // ---- stage input for this lane's element (packed) ----
            u64 sxy;
            if (st == 0) {
                sxy = yv;
            } else {
                u64 a = 0ull;
                for (int i = 0; i < st; i++) {
                    const float2 c = cA2[st - 1][i];
                    a = fma2(*(const u64*)&c, kreg[i], a);
                }
                sxy = fma2(dtp, a, yv);
            }
            float sx, sy;
            upk(sxy, sx, sy);

            __syncwarp();   // prior stage's h readers done (WAR)

            // ---- layer 1: 8 units u0..u0+7 for element me ----
            {
                const float4 wxA = *(const float4*)&sW1x[u0];
                const float4 wxB = *(const float4*)&sW1x[u0 + 4];
                const float4 wyA = *(const float4*)&sW1y[u0];
                const float4 wyB = *(const float4*)&sW1y[u0 + 4];
                const float4 bA = *(const float4*)&sB1[u0];
                const float4 bB = *(const float4*)&sB1[u0 + 4];
                float4 hA, hB;
                hA.x = tanh_pre(fmaf(sx, wxA.x, fmaf(sy, wyA.x, bA.x)));
                hA.y = tanh_pre(fmaf(sx, wxA.y, fmaf(sy, wyA.y, bA.y)));
                hA.z = tanh_pre(fmaf(sx, wxA.z, fmaf(sy, wyA.z, bA.z)));
                hA.w = tanh_pre(fmaf(sx, wxA.w, fmaf(sy, wyA.w, bA.w)));
                hB.x = tanh_pre(fmaf(sx, wxB.x, fmaf(sy, wyB.x, bB.x)));
                hB.y = tanh_pre(fmaf(sx, wxB.y, fmaf(sy, wyB.y, bB.y)));
                hB.z = tanh_pre(fmaf(sx, wxB.z, fmaf(sy, wyB.z, bB.z)));
                hB.w = tanh_pre(fmaf(sx, wxB.w, fmaf(sy, wyB.w, bB.w)));
                *(float4*)&hme[u0] = hA;
                *(float4*)&hme[u0 + 4] = hB;
            }
            __syncwarp();   // h complete (RAW)

            // ---- layer 2: 4 elements x 2 j, k-parity packed ----
            u64 acc[4][2];
#pragma unroll
            for (int m = 0; m < 4; m++) { acc[m][0] = 0ull; acc[m][1] = 0ull; }
#pragma unroll
            for (int q = 0; q < 16; q++) {
                const u64 wA0 = w2r[0][2 * q], wA1 = w2r[0][2 * q + 1];
                const u64 wB0 = w2r[1][2 * q], wB1 = w2r[1][2 * q + 1];
#pragma unroll
                for (int m = 0; m < 4; m++) {
                    const float4 hq = *(const float4*)&hw[m * HH + 4 * q];
                    const u64 pA = ((const u64*)&hq)[0];
                    const u64 pB = ((const u64*)&hq)[1];
                    acc[m][0] = fma2(pA, wA0, acc[m][0]);
                    acc[m][1] = fma2(pA, wB0, acc[m][1]);
                    acc[m][0] = fma2(pB, wA1, acc[m][0]);
                    acc[m][1] = fma2(pB, wB1, acc[m][1]);
                }
            }

            // ---- phase D: merge parities, bias, tanh, layer 3 ----
            u64 accP[4];
#pragma unroll
            for (int m = 0; m < 4; m++) {
                float l, h;
                upk(acc[m][0], l, h);
                const float g0 = tanh_pre(l + h + b2r0);
                upk(acc[m][1], l, h);
                const float g1 = tanh_pre(l + h + b2r1);
                accP[m] = fma2(dup2(g0), w3r0, fma2(dup2(g1), w3r1, 0ull));
            }

            // ---- split-butterfly: lane ends with f(own element me) ----
            const u64 g0v = b4 ? accP[0] : accP[2];
            const u64 g1v = b4 ? accP[1] : accP[3];
            const u64 k0v = b4 ? accP[2] : accP[0];
            const u64 k1v = b4 ? accP[3] : accP[1];
            const u64 r0 = add2(k0v, shfl_xor64(g0v, 16));
            const u64 r1 = add2(k1v, shfl_xor64(g1v, 16));
            const u64 gv = b3b ? r0 : r1;
            const u64 kv = b3b ? r1 : r0;
            u64 s = add2(kv, shfl_xor64(gv, 8));
            s = add2(s, shfl_xor64(s, 4));
            s = add2(s, shfl_xor64(s, 2));
            s = add2(s, shfl_xor64(s, 1));
            kreg[st] = add2(s, b3p);
        }

        // ---- combine and advance (packed; every lane owns element me) ----
        u64 comb = fma2(*(const u64*)&cB2[0], kreg[0], 0ull);
        comb = fma2(*(const u64*)&cB2[1], kreg[2], comb);
        comb = fma2(*(const u64*)&cB2[2], kreg[3], comb);
        comb = fma2(*(const u64*)&cB2[3], kreg[4], comb);
        comb = fma2(*(const u64*)&cB2[4], kreg[5], comb);
        yv = fma2(dtp, comb, yv);

        if (o == 0)
            o8[(size_t)(t + 1) * NB + em] = yv;
    }
}

extern "C" void kernel_launch(void* const* d_in, const int* in_sizes, int n_in,
                              void* d_out, int out_size) {
    const float* y0 = (const float*)d_in[0];
    const float* ts = (const float*)d_in[1];
    const float* W1 = (const float*)d_in[2];
    const float* b1 = (const float*)d_in[3];
    const float* W2 = (const float*)d_in[4];
    const float* b2 = (const float*)d_in[5];
    const float* W3 = (const float*)d_in[6];
    const float* b3 = (const float*)d_in[7];
    ode_kernel<<<GRID, TPB>>>(y0, ts, W1, b1, W2, b2, W3, b3, (float*)d_out);
}